// round 2
// baseline (speedup 1.0000x reference)
#include <cuda_runtime.h>
#include <math.h>

#define S_LEN 2048
#define NH    8
#define NB    2
#define DH    64
#define PM    132   // padded transposed-tile row pitch (floats)

__device__ __forceinline__ unsigned long long dup2(float x){
  unsigned long long r;
  asm("mov.b64 %0, {%1, %1};" : "=l"(r) : "f"(x));
  return r;
}
__device__ __forceinline__ void ffma2(unsigned long long &c, unsigned long long a, unsigned long long b){
  asm("fma.rn.f32x2 %0, %1, %2, %0;" : "+l"(c) : "l"(a), "l"(b));
}
__device__ __forceinline__ float2 unpk(unsigned long long v){
  float2 f;
  asm("mov.b64 {%0, %1}, %2;" : "=f"(f.x), "=f"(f.y) : "l"(v));
  return f;
}

extern __shared__ float smem1[];

// Kernel 1: raw QK^T (fp32) with mask applied (-1e9), written into P region.
__global__ __launch_bounds__(256, 2)
void qk_kernel(const float* __restrict__ Q, const float* __restrict__ K,
               const int* __restrict__ mask, float* __restrict__ P)
{
  float* Qs = smem1;              // [64][PM], transposed: Qs[k][m]
  float* Ks = smem1 + 64 * PM;    // [64][PM]
  const int bh = blockIdx.z;
  const int tm = blockIdx.y << 7;
  const int tn = blockIdx.x << 7;
  const float* Qb = Q + ((size_t)bh * S_LEN + tm) * DH;
  const float* Kb = K + ((size_t)bh * S_LEN + tn) * DH;
  const int t = threadIdx.x;

  // Load 128x64 tiles, transposing into smem.
  #pragma unroll
  for (int i = 0; i < 8; i++){
    int idx = (i << 8) + t;          // 0..2047
    int row = idx >> 4;              // 0..127
    int kc  = (idx & 15) << 2;       // 0..60 step 4
    float4 q = *(const float4*)(Qb + row * DH + kc);
    Qs[(kc+0)*PM + row] = q.x; Qs[(kc+1)*PM + row] = q.y;
    Qs[(kc+2)*PM + row] = q.z; Qs[(kc+3)*PM + row] = q.w;
    float4 kk = *(const float4*)(Kb + row * DH + kc);
    Ks[(kc+0)*PM + row] = kk.x; Ks[(kc+1)*PM + row] = kk.y;
    Ks[(kc+2)*PM + row] = kk.z; Ks[(kc+3)*PM + row] = kk.w;
  }
  __syncthreads();

  const int w = t >> 5, lane = t & 31;
  const int wm = w >> 2, wn = w & 3;          // warps 2x4 over the 128x128 tile
  const int lm = lane >> 2, ln = lane & 3;    // lanes 8x4 inside a 64x32 warp tile
  const int m0 = (wm << 6) + (lm << 3);       // 8 m-rows per thread
  const int n0 = (wn << 5) + (ln << 3);       // 8 n-cols per thread

  // acc[r][c] packs rows (m0+2r, m0+2r+1) for column n0+c
  unsigned long long acc[4][8];
  #pragma unroll
  for (int i = 0; i < 4; i++)
    #pragma unroll
    for (int j = 0; j < 8; j++) acc[i][j] = 0ULL;

  #pragma unroll 16
  for (int k = 0; k < 64; k++){
    const float* qp = &Qs[k * PM + m0];
    const float* kp = &Ks[k * PM + n0];
    ulonglong2 a01 = *(const ulonglong2*)(qp);      // (m0,m0+1),(m0+2,m0+3)
    ulonglong2 a23 = *(const ulonglong2*)(qp + 4);
    float4 b0 = *(const float4*)(kp);
    float4 b1 = *(const float4*)(kp + 4);
    unsigned long long ap[4] = {a01.x, a01.y, a23.x, a23.y};
    unsigned long long bd[8] = {dup2(b0.x), dup2(b0.y), dup2(b0.z), dup2(b0.w),
                                dup2(b1.x), dup2(b1.y), dup2(b1.z), dup2(b1.w)};
    #pragma unroll
    for (int r = 0; r < 4; r++)
      #pragma unroll
      for (int c = 0; c < 8; c++)
        ffma2(acc[r][c], ap[r], bd[c]);
  }

  // Epilogue: apply mask, store raw qk (masked -> -1e9) to P.
  const int b = bh >> 3;   // NH = 8
  int mk[8];
  #pragma unroll
  for (int j = 0; j < 8; j++) mk[j] = mask[b * S_LEN + tn + n0 + j];
  #pragma unroll
  for (int r = 0; r < 4; r++){
    float v0[8], v1[8];
    #pragma unroll
    for (int c = 0; c < 8; c++){
      float2 f = unpk(acc[r][c]);
      v0[c] = mk[c] ? f.x : -1e9f;
      v1[c] = mk[c] ? f.y : -1e9f;
    }
    size_t base = ((size_t)bh * S_LEN + tm + m0 + 2*r) * S_LEN + tn + n0;
    *(float4*)(P + base)             = *(float4*)(v0);
    *(float4*)(P + base + 4)         = *(float4*)(v0 + 4);
    *(float4*)(P + base + S_LEN)     = *(float4*)(v1);
    *(float4*)(P + base + S_LEN + 4) = *(float4*)(v1 + 4);
  }
}

// Kernel 2: per-row exact softmax of exp(qk)/8 (masked entries are -1e9 in P),
// rewrite P with probabilities, compute out = p @ V.
__global__ __launch_bounds__(256)
void softmax_pv(const float* __restrict__ V, float* __restrict__ P,
                float* __restrict__ Out)
{
  __shared__ float red[8];
  __shared__ float sout[DH];
  __shared__ float sh_max, sh_sum;
  const int row = blockIdx.x;          // 0..B*H*S-1
  const int bh  = row >> 11;           // /S_LEN
  const int t = threadIdx.x;
  const int w = t >> 5, lane = t & 31;
  float* Pr = P + (size_t)row * S_LEN;

  float4 c0 = *(const float4*)(Pr + (t << 2));
  float4 c1 = *(const float4*)(Pr + 1024 + (t << 2));
  float qk[8] = {c0.x, c0.y, c0.z, c0.w, c1.x, c1.y, c1.z, c1.w};

  float mx = qk[0];
  #pragma unroll
  for (int i = 1; i < 8; i++) mx = fmaxf(mx, qk[i]);
  #pragma unroll
  for (int off = 16; off; off >>= 1) mx = fmaxf(mx, __shfl_xor_sync(0xffffffffu, mx, off));
  if (lane == 0) red[w] = mx;
  if (t < DH) sout[t] = 0.0f;
  __syncthreads();
  if (t == 0){
    float m = red[0];
    #pragma unroll
    for (int i = 1; i < 8; i++) m = fmaxf(m, red[i]);
    sh_max = m;
  }
  __syncthreads();
  const float qkmax = sh_max;
  // s(x): reference semantics. masked (-1e9) stays -1e9, else exp(x)/8.
  const float smax = (qkmax <= -1e8f) ? -1e9f : expf(qkmax) * 0.125f;
  // Guaranteed-underflow cutoff: if qkmax>12, any qk below qkmax-0.125 gives
  // s_max - s >= (1-e^-0.125)*e^12/8 > 2000 -> exp() == 0.0f exactly.
  const float cutq = (qkmax > 12.0f) ? qkmax - 0.125f : -3.0e38f;

  float e[8];
  float lsum = 0.0f;
  #pragma unroll
  for (int i = 0; i < 8; i++){
    e[i] = 0.0f;
    if (qk[i] >= cutq){
      float si = (qk[i] <= -1e8f) ? -1e9f : expf(qk[i]) * 0.125f;
      e[i] = expf(si - smax);
      lsum += e[i];
    }
  }
  #pragma unroll
  for (int off = 16; off; off >>= 1) lsum += __shfl_xor_sync(0xffffffffu, lsum, off);
  if (lane == 0) red[w] = lsum;
  __syncthreads();
  if (t == 0){
    float s = 0.0f;
    #pragma unroll
    for (int i = 0; i < 8; i++) s += red[i];
    sh_sum = s;
  }
  __syncthreads();
  const float inv = 1.0f / sh_sum;

  float p[8];
  #pragma unroll
  for (int i = 0; i < 8; i++) p[i] = e[i] * inv;
  *(float4*)(Pr + (t << 2))        = make_float4(p[0], p[1], p[2], p[3]);
  *(float4*)(Pr + 1024 + (t << 2)) = make_float4(p[4], p[5], p[6], p[7]);

  const float* Vb = V + (size_t)bh * S_LEN * DH;
  #pragma unroll
  for (int i = 0; i < 8; i++){
    if (e[i] != 0.0f){
      int key = (i < 4) ? ((t << 2) + i) : (1024 + (t << 2) + (i - 4));
      const float* vr = Vb + (size_t)key * DH;
      float pi = p[i];
      for (int d = 0; d < DH; d++) atomicAdd(&sout[d], pi * vr[d]);
    }
  }
  __syncthreads();
  if (t < DH) Out[(size_t)row * DH + t] = sout[t];
}

extern "C" void kernel_launch(void* const* d_in, const int* in_sizes, int n_in,
                              void* d_out, int out_size)
{
  const float* Q    = (const float*)d_in[0];
  const float* K    = (const float*)d_in[1];
  const float* V    = (const float*)d_in[2];
  const int*   mask = (const int*)d_in[3];

  float* Out = (float*)d_out;                              // (B,H,S,D) = 2M floats
  float* P   = Out + (size_t)NB * NH * S_LEN * DH;         // (B,H,S,S) = 64M floats

  const int smem = 2 * 64 * PM * sizeof(float);            // 67.6 KB
  cudaFuncSetAttribute(qk_kernel, cudaFuncAttributeMaxDynamicSharedMemorySize, smem);

  dim3 g1(S_LEN / 128, S_LEN / 128, NB * NH);              // 16 x 16 x 16
  qk_kernel<<<g1, 256, smem>>>(Q, K, mask, P);
  softmax_pv<<<NB * NH * S_LEN, 256>>>(V, P, Out);
}